// round 3
// baseline (speedup 1.0000x reference)
#include <cuda_runtime.h>
#include <math.h>

#define BATCH   8
#define NPTS    8192
#define NPOINT  2048
#define NSAMPLE 32

#define FPS_CLUSTER 8
#define FPS_THREADS 256
#define FPS_PPT     4          // (NPTS / FPS_CLUSTER) / FPS_THREADS
#define FPS_SENT    0xFFFFFFFFFFFFFFFFull

// ---------------- scratch (no allocation allowed) ----------------
__device__ int   g_ball_idx[BATCH * NPOINT * NSAMPLE];
__device__ float g_fw1[64 * 68];
__device__ float g_fb1[64];
__device__ float g_fw2[64 * 64];
__device__ float g_fb2[64];
__device__ float g_fw3[128 * 64];
__device__ float g_fb3[128];

// ---------------- cluster DSMEM helpers ----------------
__device__ __forceinline__ void st_remote_release_u64(unsigned int local_saddr,
                                                      unsigned int rank,
                                                      unsigned long long v)
{
    asm volatile(
        "{ .reg .b32 ra;\n\t"
        "  mapa.shared::cluster.u32 ra, %0, %1;\n\t"
        "  st.release.cluster.shared::cluster.u64 [ra], %2; }"
        :: "r"(local_saddr), "r"(rank), "l"(v) : "memory");
}

__device__ __forceinline__ unsigned long long ld_acquire_u64(unsigned int saddr)
{
    unsigned long long v;
    asm volatile("ld.acquire.cluster.shared::cta.u64 %0, [%1];"
                 : "=l"(v) : "r"(saddr) : "memory");
    return v;
}

// ---------------- fold BN-affine into weights ----------------
__global__ void prep_kernel(const float* __restrict__ w1, const float* __restrict__ b1,
                            const float* __restrict__ g1, const float* __restrict__ bt1,
                            const float* __restrict__ w2, const float* __restrict__ b2,
                            const float* __restrict__ g2, const float* __restrict__ bt2,
                            const float* __restrict__ w3, const float* __restrict__ b3,
                            const float* __restrict__ g3, const float* __restrict__ bt3)
{
    int t = blockIdx.x * blockDim.x + threadIdx.x;
    int stride = gridDim.x * blockDim.x;
    const float inv = 1.0f / sqrtf(1.0f + 1e-5f);
    for (int i = t; i < 64 * 68; i += stride) {
        int o = i / 68, c = i % 68;
        g_fw1[i] = (c < 67) ? (g1[o] * inv) * w1[o * 67 + c] : 0.0f;
    }
    for (int i = t; i < 64 * 64; i += stride) {
        int o = i >> 6;
        g_fw2[i] = (g2[o] * inv) * w2[i];
    }
    for (int i = t; i < 128 * 64; i += stride) {
        int o = i >> 6;
        g_fw3[i] = (g3[o] * inv) * w3[i];
    }
    for (int i = t; i < 64; i += stride) {
        g_fb1[i] = (g1[i] * inv) * b1[i] + bt1[i];
        g_fb2[i] = (g2[i] * inv) * b2[i] + bt2[i];
    }
    for (int i = t; i < 128; i += stride)
        g_fb3[i] = (g3[i] * inv) * b3[i] + bt3[i];
}

// ---------------- farthest point sampling (8-CTA cluster per batch) ----------------
// Cluster of 8 CTAs per batch (64 CTAs total -> 64 SMs). Each CTA owns 1024
// points (4/thread) but keeps a FULL smem copy of xyz for centroid lookup.
// Per iteration: each CTA reduces its 1024 points to one u64 key
//   key = (dist_bits << 32) | (8191 - idx)
// (dist >= 0 so float bits are order-monotonic; u64-max => max dist, tie -> min idx,
// exactly jnp.argmax semantics). The leader release-stores its key into slot
// arrays of ALL 8 cluster CTAs (single DSMEM hop); every CTA's thread0
// acquire-polls its 8 local slots, reduces, and announces the winner in a
// tag-encoded local word that all threads spin on.
//
// Slot reuse safety: slots are double-buffered by (it & 1) and reset to a
// sentinel by the consuming thread0 right after it observed them. The next
// write to that bank (it+2) is ordered after the writer's acquire of this
// CTA's it+1 store, which is release-ordered after the reset -> no race.
// Distance math uses explicit rn sub/mul/add in x,y,z order (no FMA) so every
// distance is bitwise identical to the XLA reference.
__global__ void __launch_bounds__(FPS_THREADS, 1) __cluster_dims__(FPS_CLUSTER, 1, 1)
fps_kernel(const float* __restrict__ xyz, float* __restrict__ out_xyz)
{
    extern __shared__ float sm[];
    float* sx = sm;
    float* sy = sm + NPTS;
    float* sz = sm + 2 * NPTS;
    __shared__ unsigned long long slots[2][FPS_CLUSTER];
    __shared__ unsigned long long red[FPS_THREADS / 32];
    __shared__ volatile unsigned int announce;

    int tid  = threadIdx.x;
    int rank = blockIdx.x & (FPS_CLUSTER - 1);   // == %cluster_ctarank for x-clusters
    int b    = blockIdx.x / FPS_CLUSTER;
    const float* xb = xyz + (size_t)b * NPTS * 3;

    // full xyz copy into smem
    for (int p = tid; p < NPTS; p += FPS_THREADS) {
        sx[p] = xb[3 * p];
        sy[p] = xb[3 * p + 1];
        sz[p] = xb[3 * p + 2];
    }
    if (tid < FPS_CLUSTER) {
        slots[0][tid] = FPS_SENT;
        slots[1][tid] = FPS_SENT;
    }
    if (tid == 0) announce = 0u;
    __syncthreads();
    // all CTAs' smem (slots) must be initialized before any remote store lands
    asm volatile("barrier.cluster.arrive.aligned;" ::: "memory");
    asm volatile("barrier.cluster.wait.aligned;"   ::: "memory");

    // own points
    int base = rank * (NPTS / FPS_CLUSTER) + tid * FPS_PPT;
    float px[FPS_PPT], py[FPS_PPT], pz[FPS_PPT], dist[FPS_PPT];
#pragma unroll
    for (int j = 0; j < FPS_PPT; j++) {
        px[j] = sx[base + j];
        py[j] = sy[base + j];
        pz[j] = sz[base + j];
        dist[j] = 1e10f;
    }

    unsigned int slot_base = (unsigned int)__cvta_generic_to_shared(&slots[0][0]);
    int lane = tid & 31, w = tid >> 5;
    int far = 0;
    float* ob = out_xyz + (size_t)b * NPOINT * 3;

    for (int it = 0; it < NPOINT; it++) {
        float cx = sx[far], cy = sy[far], cz = sz[far];
        if (rank == 0 && tid == 0) {
            ob[3 * it] = cx; ob[3 * it + 1] = cy; ob[3 * it + 2] = cz;
        }

        float bv = -1.0f; int bi = 0;
#pragma unroll
        for (int j = 0; j < FPS_PPT; j++) {
            float dx = __fsub_rn(px[j], cx);
            float dy = __fsub_rn(py[j], cy);
            float dz = __fsub_rn(pz[j], cz);
            float d  = __fmul_rn(dx, dx);
            d = __fadd_rn(d, __fmul_rn(dy, dy));
            d = __fadd_rn(d, __fmul_rn(dz, dz));
            float nd = fminf(dist[j], d);
            dist[j] = nd;
            if (nd > bv) { bv = nd; bi = base + j; }   // ascending idx: > keeps first
        }
        // warp reduce (max val, tie -> min idx)
#pragma unroll
        for (int off = 16; off > 0; off >>= 1) {
            float ov = __shfl_down_sync(0xffffffffu, bv, off);
            int   oi = __shfl_down_sync(0xffffffffu, bi, off);
            if (ov > bv || (ov == bv && oi < bi)) { bv = ov; bi = oi; }
        }
        if (lane == 0)
            red[w] = ((unsigned long long)__float_as_uint(bv) << 32)
                   | (unsigned int)(NPTS - 1 - bi);
        __syncthreads();

        int bank = it & 1;
        if (tid == 0) {
            unsigned long long k = red[0];
#pragma unroll
            for (int i = 1; i < FPS_THREADS / 32; i++)
                if (red[i] > k) k = red[i];

            unsigned int my_slot = slot_base + (unsigned int)((bank * FPS_CLUSTER + rank) * 8);
#pragma unroll
            for (int r = 0; r < FPS_CLUSTER; r++)
                st_remote_release_u64(my_slot, (unsigned int)r, k);

            unsigned long long best = 0ull;
#pragma unroll
            for (int r = 0; r < FPS_CLUSTER; r++) {
                unsigned int a = slot_base + (unsigned int)((bank * FPS_CLUSTER + r) * 8);
                unsigned long long v;
                do { v = ld_acquire_u64(a); } while (v == FPS_SENT);
                if (v > best) best = v;
                slots[bank][r] = FPS_SENT;           // consumed -> reset
            }
            int far_next = NPTS - 1 - (int)(unsigned int)best;
            announce = ((unsigned int)(it + 1) << 16) | (unsigned int)far_next;
        }
        unsigned int want = (unsigned int)(it + 1) << 16;
        unsigned int a;
        do { a = announce; } while ((a & 0xFFFF0000u) != want);
        far = (int)(a & 0xFFFFu);
    }
    // no CTA may exit while peers might still target its smem
    asm volatile("barrier.cluster.arrive.aligned;" ::: "memory");
    asm volatile("barrier.cluster.wait.aligned;"   ::: "memory");
}

// ---------------- ball query ----------------
// Warp per centroid. Indices are naturally ascending, so "sort then take
// first NSAMPLE" == scan in order collecting first NSAMPLE hits. Early exit.
__global__ void __launch_bounds__(256)
ballq_kernel(const float* __restrict__ xyz, const float* __restrict__ cxyz)
{
    __shared__ int sidx[8][NSAMPLE];
    int warp = threadIdx.x >> 5, lane = threadIdx.x & 31;
    int g = blockIdx.x * 8 + warp;          // 0 .. BATCH*NPOINT-1
    int b = g >> 11;

    const float* cp = cxyz + (size_t)g * 3;
    float cx = cp[0], cy = cp[1], cz = cp[2];
    const float* xb = xyz + (size_t)b * NPTS * 3;
    const float r2 = (float)(0.2 * 0.2);    // matches JAX weak-typed python scalar
    unsigned ltmask = (1u << lane) - 1u;

    int count = 0;
    for (int base = 0; base < NPTS; base += 32) {
        int p = base + lane;
        float xv = xb[3 * p], yv = xb[3 * p + 1], zv = xb[3 * p + 2];
        float dx = __fsub_rn(cx, xv);
        float dy = __fsub_rn(cy, yv);
        float dz = __fsub_rn(cz, zv);
        float d  = __fmul_rn(dx, dx);
        d = __fadd_rn(d, __fmul_rn(dy, dy));
        d = __fadd_rn(d, __fmul_rn(dz, dz));
        int in = (d <= r2) ? 1 : 0;         // == !(d > r2), reference semantics
        unsigned m = __ballot_sync(0xffffffffu, in);
        if (in) {
            int pos = count + __popc(m & ltmask);
            if (pos < NSAMPLE) sidx[warp][pos] = p;
        }
        count += __popc(m);
        if (count >= NSAMPLE) break;        // warp-uniform
    }
    __syncwarp();
    int v = (lane < count) ? sidx[warp][lane] : sidx[warp][0];  // pad with first
    g_ball_idx[(size_t)g * NSAMPLE + lane] = v;
}

// ---------------- fused 3-layer MLP + max-pool ----------------
// 128 threads = 4 warps, warp per centroid, lane per sample.
// Folded weights staged in shared (float4 loads: 1 LDS.128 per 4 FFMA).
// x / y1 / y2 live fully in registers (full unroll), warp-shuffle max fused
// into layer 3 so y3 never needs 128 registers.
__global__ void __launch_bounds__(128, 3)
mlp_kernel(const float* __restrict__ xyz, const float* __restrict__ feats,
           const float* __restrict__ cxyz, float* __restrict__ out_feats)
{
    extern __shared__ float swm[];
    float* sw1 = swm;                 // 64*68
    float* sw2 = sw1 + 64 * 68;       // 64*64
    float* sw3 = sw2 + 64 * 64;       // 128*64
    float* sb1 = sw3 + 128 * 64;      // 64
    float* sb2 = sb1 + 64;            // 64
    float* sb3 = sb2 + 64;            // 128

    int tid = threadIdx.x;
    for (int i = tid; i < 64 * 68;  i += 128) sw1[i] = g_fw1[i];
    for (int i = tid; i < 64 * 64;  i += 128) sw2[i] = g_fw2[i];
    for (int i = tid; i < 128 * 64; i += 128) sw3[i] = g_fw3[i];
    if (tid < 64)  { sb1[tid] = g_fb1[tid]; sb2[tid] = g_fb2[tid]; }
    if (tid < 128)   sb3[tid] = g_fb3[tid];
    __syncthreads();

    int warp = tid >> 5, lane = tid & 31;
    int g = blockIdx.x * 4 + warp;
    int b = g >> 11, s = g & 2047;

    const float* cp = cxyz + (size_t)(b * NPOINT + s) * 3;
    float cx = cp[0], cy = cp[1], cz = cp[2];
    int idx = g_ball_idx[(size_t)g * NSAMPLE + lane];
    const float* pp = xyz + (size_t)(b * NPTS + idx) * 3;

    float x[68];
    x[0] = (pp[0] - cx) / 0.2f;
    x[1] = (pp[1] - cy) / 0.2f;
    x[2] = (pp[2] - cz) / 0.2f;
    const float4* pf = (const float4*)(feats + (size_t)(b * NPTS + idx) * 64);
#pragma unroll
    for (int q = 0; q < 16; q++) {
        float4 f = pf[q];
        x[3 + 4 * q] = f.x; x[4 + 4 * q] = f.y;
        x[5 + 4 * q] = f.z; x[6 + 4 * q] = f.w;
    }
    x[67] = 0.0f;

    float y1[64];
#pragma unroll
    for (int o = 0; o < 64; o++) {
        float acc = sb1[o];
        const float4* wv = (const float4*)(sw1 + o * 68);
#pragma unroll
        for (int q = 0; q < 17; q++) {
            float4 w = wv[q];
            acc = fmaf(w.x, x[4 * q + 0], acc);
            acc = fmaf(w.y, x[4 * q + 1], acc);
            acc = fmaf(w.z, x[4 * q + 2], acc);
            acc = fmaf(w.w, x[4 * q + 3], acc);
        }
        y1[o] = fmaxf(acc, 0.0f);
    }

    float y2[64];
#pragma unroll
    for (int o = 0; o < 64; o++) {
        float acc = sb2[o];
        const float4* wv = (const float4*)(sw2 + o * 64);
#pragma unroll
        for (int q = 0; q < 16; q++) {
            float4 w = wv[q];
            acc = fmaf(w.x, y1[4 * q + 0], acc);
            acc = fmaf(w.y, y1[4 * q + 1], acc);
            acc = fmaf(w.z, y1[4 * q + 2], acc);
            acc = fmaf(w.w, y1[4 * q + 3], acc);
        }
        y2[o] = fmaxf(acc, 0.0f);
    }

    float rr[4];
#pragma unroll
    for (int o = 0; o < 128; o++) {
        float acc = sb3[o];
        const float4* wv = (const float4*)(sw3 + o * 64);
#pragma unroll
        for (int q = 0; q < 16; q++) {
            float4 w = wv[q];
            acc = fmaf(w.x, y2[4 * q + 0], acc);
            acc = fmaf(w.y, y2[4 * q + 1], acc);
            acc = fmaf(w.z, y2[4 * q + 2], acc);
            acc = fmaf(w.w, y2[4 * q + 3], acc);
        }
        acc = fmaxf(acc, 0.0f);
        // max over the 32 samples (butterfly: every lane ends with the max)
#pragma unroll
        for (int off = 16; off > 0; off >>= 1)
            acc = fmaxf(acc, __shfl_xor_sync(0xffffffffu, acc, off));
        if (lane == (o & 31)) rr[o >> 5] = acc;
    }
    float* ob = out_feats + (size_t)(b * NPOINT + s) * 128;
#pragma unroll
    for (int j = 0; j < 4; j++) ob[j * 32 + lane] = rr[j];
}

// ---------------- launch ----------------
extern "C" void kernel_launch(void* const* d_in, const int* in_sizes, int n_in,
                              void* d_out, int out_size)
{
    const float* xyz   = (const float*)d_in[0];
    const float* feats = (const float*)d_in[1];

    float* out       = (float*)d_out;
    float* out_xyz   = out;                          // [B, NPOINT, 3]
    float* out_feats = out + BATCH * NPOINT * 3;     // [B, NPOINT, 128]

    cudaFuncSetAttribute(fps_kernel, cudaFuncAttributeMaxDynamicSharedMemorySize, 3 * NPTS * 4);
    cudaFuncSetAttribute(mlp_kernel, cudaFuncAttributeMaxDynamicSharedMemorySize, 67584);

    prep_kernel<<<32, 256>>>((const float*)d_in[2],  (const float*)d_in[3],
                             (const float*)d_in[4],  (const float*)d_in[5],
                             (const float*)d_in[6],  (const float*)d_in[7],
                             (const float*)d_in[8],  (const float*)d_in[9],
                             (const float*)d_in[10], (const float*)d_in[11],
                             (const float*)d_in[12], (const float*)d_in[13]);

    fps_kernel<<<BATCH * FPS_CLUSTER, FPS_THREADS, 3 * NPTS * 4>>>(xyz, out_xyz);

    ballq_kernel<<<(BATCH * NPOINT) / 8, 256>>>(xyz, out_xyz);

    mlp_kernel<<<(BATCH * NPOINT) / 4, 128, 67584>>>(xyz, feats, out_xyz, out_feats);
}

// round 5
// speedup vs baseline: 2.9536x; 2.9536x over previous
#include <cuda_runtime.h>
#include <math.h>

#define BATCH   8
#define NPTS    8192
#define NPOINT  2048
#define NSAMPLE 32

// ---------------- scratch (no allocation allowed) ----------------
__device__ int   g_ball_idx[BATCH * NPOINT * NSAMPLE];
__device__ float g_fw1[64 * 68];
__device__ float g_fb1[64];
__device__ float g_fw2[64 * 64];
__device__ float g_fb2[64];
__device__ float g_fw3[128 * 64];
__device__ float g_fb3[128];

// ---------------- packed f32x2 helpers (per-lane rn => bitwise == scalar) ---
__device__ __forceinline__ unsigned long long pk2(float lo, float hi) {
    unsigned long long r;
    asm("mov.b64 %0, {%1, %2};" : "=l"(r) : "f"(lo), "f"(hi));
    return r;
}
__device__ __forceinline__ void upk2(float& lo, float& hi, unsigned long long v) {
    asm("mov.b64 {%0, %1}, %2;" : "=f"(lo), "=f"(hi) : "l"(v));
}
__device__ __forceinline__ unsigned long long add2(unsigned long long a, unsigned long long b) {
    unsigned long long r;
    asm("add.rn.f32x2 %0, %1, %2;" : "=l"(r) : "l"(a), "l"(b));
    return r;
}
__device__ __forceinline__ unsigned long long mul2(unsigned long long a, unsigned long long b) {
    unsigned long long r;
    asm("mul.rn.f32x2 %0, %1, %2;" : "=l"(r) : "l"(a), "l"(b));
    return r;
}

// ---------------- fold BN-affine into weights ----------------
__global__ void prep_kernel(const float* __restrict__ w1, const float* __restrict__ b1,
                            const float* __restrict__ g1, const float* __restrict__ bt1,
                            const float* __restrict__ w2, const float* __restrict__ b2,
                            const float* __restrict__ g2, const float* __restrict__ bt2,
                            const float* __restrict__ w3, const float* __restrict__ b3,
                            const float* __restrict__ g3, const float* __restrict__ bt3)
{
    int t = blockIdx.x * blockDim.x + threadIdx.x;
    int stride = gridDim.x * blockDim.x;
    const float inv = 1.0f / sqrtf(1.0f + 1e-5f);
    for (int i = t; i < 64 * 68; i += stride) {
        int o = i / 68, c = i % 68;
        g_fw1[i] = (c < 67) ? (g1[o] * inv) * w1[o * 67 + c] : 0.0f;
    }
    for (int i = t; i < 64 * 64; i += stride) {
        int o = i >> 6;
        g_fw2[i] = (g2[o] * inv) * w2[i];
    }
    for (int i = t; i < 128 * 64; i += stride) {
        int o = i >> 6;
        g_fw3[i] = (g3[o] * inv) * w3[i];
    }
    for (int i = t; i < 64; i += stride) {
        g_fb1[i] = (g1[i] * inv) * b1[i] + bt1[i];
        g_fb2[i] = (g2[i] * inv) * b2[i] + bt2[i];
    }
    for (int i = t; i < 128; i += stride)
        g_fb3[i] = (g3[i] * inv) * b3[i] + bt3[i];
}

// ---------------- farthest point sampling ----------------
// One 1024-thread block per batch (8 SMs busy; cluster variants lose to sync
// cost — measured R3). Blocked assignment: thread owns 8 consecutive points,
// so lane order == index order == warp order (tie-break = lowest index, i.e.
// jnp.argmax "first max"). Distance math: packed f32x2 add/mul with per-lane
// rn — bitwise identical to the XLA scalar sequence (dx*dx; +dy*dy; +dz*dz),
// using p + (-c) which is IEEE-exact p - c. Distances are >= +0, so float
// order == unsigned-bit order: argmax runs on u32 bits with REDUX + ballot.
__global__ void __launch_bounds__(1024, 1)
fps_kernel(const float* __restrict__ xyz, float* __restrict__ out_xyz)
{
    extern __shared__ float sm[];
    float* sx = sm;
    float* sy = sm + NPTS;
    float* sz = sm + 2 * NPTS;
    __shared__ unsigned red_v[32];
    __shared__ int      red_i[32];
    __shared__ int      s_far;

    int b = blockIdx.x, tid = threadIdx.x;
    const float* xb = xyz + (size_t)b * NPTS * 3;

    for (int p = tid; p < NPTS; p += 1024) {
        sx[p] = xb[3 * p];
        sy[p] = xb[3 * p + 1];
        sz[p] = xb[3 * p + 2];
    }
    __syncthreads();

    int base = tid * 8;
    unsigned long long pxp[4], pyp[4], pzp[4];
    float dist[8];
#pragma unroll
    for (int k = 0; k < 4; k++) {
        pxp[k] = pk2(sx[base + 2 * k], sx[base + 2 * k + 1]);
        pyp[k] = pk2(sy[base + 2 * k], sy[base + 2 * k + 1]);
        pzp[k] = pk2(sz[base + 2 * k], sz[base + 2 * k + 1]);
    }
#pragma unroll
    for (int j = 0; j < 8; j++) dist[j] = 1e10f;

    int lane = tid & 31, w = tid >> 5;
    int far = 0;
    float* ob = out_xyz + (size_t)b * NPOINT * 3;

    for (int it = 0; it < NPOINT; it++) {
        float cx = sx[far], cy = sy[far], cz = sz[far];
        if (tid == 0) { ob[3 * it] = cx; ob[3 * it + 1] = cy; ob[3 * it + 2] = cz; }

        unsigned long long ncx = pk2(-cx, -cx);
        unsigned long long ncy = pk2(-cy, -cy);
        unsigned long long ncz = pk2(-cz, -cz);

        unsigned umax = 0u;
#pragma unroll
        for (int k = 0; k < 4; k++) {
            unsigned long long dx = add2(pxp[k], ncx);   // == px - cx (IEEE exact)
            unsigned long long dy = add2(pyp[k], ncy);
            unsigned long long dz = add2(pzp[k], ncz);
            unsigned long long s  = mul2(dx, dx);
            s = add2(s, mul2(dy, dy));
            s = add2(s, mul2(dz, dz));
            float d0, d1;
            upk2(d0, d1, s);
            float n0 = fminf(dist[2 * k],     d0);
            float n1 = fminf(dist[2 * k + 1], d1);
            dist[2 * k]     = n0;
            dist[2 * k + 1] = n1;
            umax = umax > __float_as_uint(n0) ? umax : __float_as_uint(n0);
            umax = umax > __float_as_uint(n1) ? umax : __float_as_uint(n1);
        }

        unsigned wmax = __reduce_max_sync(0xffffffffu, umax);
        unsigned ball = __ballot_sync(0xffffffffu, umax == wmax);
        if (lane == (__ffs(ball) - 1)) {        // lowest lane = lowest index
            int bj = 7;
#pragma unroll
            for (int j = 6; j >= 0; j--)
                if (__float_as_uint(dist[j]) == wmax) bj = j;  // lowest j
            red_v[w] = wmax;
            red_i[w] = base + bj;
        }
        __syncthreads();
        if (tid < 32) {
            unsigned v = red_v[lane];
            int      ii = red_i[lane];
            unsigned m = __reduce_max_sync(0xffffffffu, v);
            unsigned bal = __ballot_sync(0xffffffffu, v == m);
            int lw = __ffs(bal) - 1;            // lowest warp = lowest index
            int f  = __shfl_sync(0xffffffffu, ii, lw);
            if (tid == 0) s_far = f;
        }
        __syncthreads();
        far = s_far;
    }
}

// ---------------- ball query ----------------
// Warp per centroid. Indices are naturally ascending, so "sort then take
// first NSAMPLE" == scan in order collecting first NSAMPLE hits. Early exit.
__global__ void __launch_bounds__(256)
ballq_kernel(const float* __restrict__ xyz, const float* __restrict__ cxyz)
{
    __shared__ int sidx[8][NSAMPLE];
    int warp = threadIdx.x >> 5, lane = threadIdx.x & 31;
    int g = blockIdx.x * 8 + warp;          // 0 .. BATCH*NPOINT-1
    int b = g >> 11;

    const float* cp = cxyz + (size_t)g * 3;
    float cx = cp[0], cy = cp[1], cz = cp[2];
    const float* xb = xyz + (size_t)b * NPTS * 3;
    const float r2 = (float)(0.2 * 0.2);    // matches JAX weak-typed python scalar
    unsigned ltmask = (1u << lane) - 1u;

    int count = 0;
    for (int base = 0; base < NPTS; base += 32) {
        int p = base + lane;
        float xv = xb[3 * p], yv = xb[3 * p + 1], zv = xb[3 * p + 2];
        float dx = __fsub_rn(cx, xv);
        float dy = __fsub_rn(cy, yv);
        float dz = __fsub_rn(cz, zv);
        float d  = __fmul_rn(dx, dx);
        d = __fadd_rn(d, __fmul_rn(dy, dy));
        d = __fadd_rn(d, __fmul_rn(dz, dz));
        int in = (d <= r2) ? 1 : 0;         // == !(d > r2), reference semantics
        unsigned m = __ballot_sync(0xffffffffu, in);
        if (in) {
            int pos = count + __popc(m & ltmask);
            if (pos < NSAMPLE) sidx[warp][pos] = p;
        }
        count += __popc(m);
        if (count >= NSAMPLE) break;        // warp-uniform
    }
    __syncwarp();
    int v = (lane < count) ? sidx[warp][lane] : sidx[warp][0];  // pad with first
    g_ball_idx[(size_t)g * NSAMPLE + lane] = v;
}

// ---------------- fused 3-layer MLP + max-pool ----------------
// 128 threads = 4 warps, warp per centroid, lane per sample.
// Folded weights staged in shared (float4 loads: 1 LDS.128 per 4 FFMA).
// Two independent accumulators per output break the FMA RAW chain (4cyc lat,
// rt 2 -> 2 in flight saturate the pipe even at 3 warps/SMSP). Outer loops
// partially unrolled so SASS fits I$. Max-pool via REDUX on relu-output bits
// (nonneg floats: bit order == float order).
__global__ void __launch_bounds__(128, 3)
mlp_kernel(const float* __restrict__ xyz, const float* __restrict__ feats,
           const float* __restrict__ cxyz, float* __restrict__ out_feats)
{
    extern __shared__ float swm[];
    float* sw1 = swm;                 // 64*68
    float* sw2 = sw1 + 64 * 68;       // 64*64
    float* sw3 = sw2 + 64 * 64;       // 128*64
    float* sb1 = sw3 + 128 * 64;      // 64
    float* sb2 = sb1 + 64;            // 64
    float* sb3 = sb2 + 64;            // 128

    int tid = threadIdx.x;
    for (int i = tid; i < 64 * 68;  i += 128) sw1[i] = g_fw1[i];
    for (int i = tid; i < 64 * 64;  i += 128) sw2[i] = g_fw2[i];
    for (int i = tid; i < 128 * 64; i += 128) sw3[i] = g_fw3[i];
    if (tid < 64)  { sb1[tid] = g_fb1[tid]; sb2[tid] = g_fb2[tid]; }
    if (tid < 128)   sb3[tid] = g_fb3[tid];
    __syncthreads();

    int warp = tid >> 5, lane = tid & 31;
    int g = blockIdx.x * 4 + warp;
    int b = g >> 11, s = g & 2047;

    const float* cp = cxyz + (size_t)(b * NPOINT + s) * 3;
    float cx = cp[0], cy = cp[1], cz = cp[2];
    int idx = g_ball_idx[(size_t)g * NSAMPLE + lane];
    const float* pp = xyz + (size_t)(b * NPTS + idx) * 3;

    float x[68];
    x[0] = (pp[0] - cx) / 0.2f;
    x[1] = (pp[1] - cy) / 0.2f;
    x[2] = (pp[2] - cz) / 0.2f;
    const float4* pf = (const float4*)(feats + (size_t)(b * NPTS + idx) * 64);
#pragma unroll
    for (int q = 0; q < 16; q++) {
        float4 f = pf[q];
        x[3 + 4 * q] = f.x; x[4 + 4 * q] = f.y;
        x[5 + 4 * q] = f.z; x[6 + 4 * q] = f.w;
    }
    x[67] = 0.0f;

    float y1[64];
#pragma unroll 4
    for (int o = 0; o < 64; o++) {
        float a0 = sb1[o], a1 = 0.0f;
        const float4* wv = (const float4*)(sw1 + o * 68);
#pragma unroll
        for (int q = 0; q < 17; q += 2) {
            float4 wa = wv[q];
            a0 = fmaf(wa.x, x[4 * q + 0], a0);
            a0 = fmaf(wa.y, x[4 * q + 1], a0);
            a0 = fmaf(wa.z, x[4 * q + 2], a0);
            a0 = fmaf(wa.w, x[4 * q + 3], a0);
            if (q + 1 < 17) {
                float4 wb = wv[q + 1];
                a1 = fmaf(wb.x, x[4 * q + 4], a1);
                a1 = fmaf(wb.y, x[4 * q + 5], a1);
                a1 = fmaf(wb.z, x[4 * q + 6], a1);
                a1 = fmaf(wb.w, x[4 * q + 7], a1);
            }
        }
        y1[o] = fmaxf(a0 + a1, 0.0f);
    }

    float y2[64];
#pragma unroll 4
    for (int o = 0; o < 64; o++) {
        float a0 = sb2[o], a1 = 0.0f;
        const float4* wv = (const float4*)(sw2 + o * 64);
#pragma unroll
        for (int q = 0; q < 16; q += 2) {
            float4 wa = wv[q];
            float4 wb = wv[q + 1];
            a0 = fmaf(wa.x, y1[4 * q + 0], a0);
            a0 = fmaf(wa.y, y1[4 * q + 1], a0);
            a0 = fmaf(wa.z, y1[4 * q + 2], a0);
            a0 = fmaf(wa.w, y1[4 * q + 3], a0);
            a1 = fmaf(wb.x, y1[4 * q + 4], a1);
            a1 = fmaf(wb.y, y1[4 * q + 5], a1);
            a1 = fmaf(wb.z, y1[4 * q + 6], a1);
            a1 = fmaf(wb.w, y1[4 * q + 7], a1);
        }
        y2[o] = fmaxf(a0 + a1, 0.0f);
    }

    float rr[4];
#pragma unroll 4
    for (int o = 0; o < 128; o++) {
        float a0 = sb3[o], a1 = 0.0f;
        const float4* wv = (const float4*)(sw3 + o * 64);
#pragma unroll
        for (int q = 0; q < 16; q += 2) {
            float4 wa = wv[q];
            float4 wb = wv[q + 1];
            a0 = fmaf(wa.x, y2[4 * q + 0], a0);
            a0 = fmaf(wa.y, y2[4 * q + 1], a0);
            a0 = fmaf(wa.z, y2[4 * q + 2], a0);
            a0 = fmaf(wa.w, y2[4 * q + 3], a0);
            a1 = fmaf(wb.x, y2[4 * q + 4], a1);
            a1 = fmaf(wb.y, y2[4 * q + 5], a1);
            a1 = fmaf(wb.z, y2[4 * q + 6], a1);
            a1 = fmaf(wb.w, y2[4 * q + 7], a1);
        }
        float acc = fmaxf(a0 + a1, 0.0f);
        // max over 32 samples: relu output >= +0 -> u32 bit order == float order
        unsigned m = __reduce_max_sync(0xffffffffu, __float_as_uint(acc));
        if (lane == (o & 31)) rr[o >> 5] = __uint_as_float(m);
    }
    float* ob = out_feats + (size_t)(b * NPOINT + s) * 128;
#pragma unroll
    for (int j = 0; j < 4; j++) ob[j * 32 + lane] = rr[j];
}

// ---------------- launch ----------------
extern "C" void kernel_launch(void* const* d_in, const int* in_sizes, int n_in,
                              void* d_out, int out_size)
{
    const float* xyz   = (const float*)d_in[0];
    const float* feats = (const float*)d_in[1];

    float* out       = (float*)d_out;
    float* out_xyz   = out;                          // [B, NPOINT, 3]
    float* out_feats = out + BATCH * NPOINT * 3;     // [B, NPOINT, 128]

    cudaFuncSetAttribute(fps_kernel, cudaFuncAttributeMaxDynamicSharedMemorySize, 3 * NPTS * 4);
    cudaFuncSetAttribute(mlp_kernel, cudaFuncAttributeMaxDynamicSharedMemorySize, 67584);

    prep_kernel<<<32, 256>>>((const float*)d_in[2],  (const float*)d_in[3],
                             (const float*)d_in[4],  (const float*)d_in[5],
                             (const float*)d_in[6],  (const float*)d_in[7],
                             (const float*)d_in[8],  (const float*)d_in[9],
                             (const float*)d_in[10], (const float*)d_in[11],
                             (const float*)d_in[12], (const float*)d_in[13]);

    fps_kernel<<<BATCH, 1024, 3 * NPTS * 4>>>(xyz, out_xyz);

    ballq_kernel<<<(BATCH * NPOINT) / 8, 256>>>(xyz, out_xyz);

    mlp_kernel<<<(BATCH * NPOINT) / 4, 128, 67584>>>(xyz, feats, out_xyz, out_feats);
}

// round 7
// speedup vs baseline: 5.1530x; 1.7446x over previous
#include <cuda_runtime.h>
#include <math.h>

#define BATCH   8
#define NPTS    8192
#define NPOINT  2048
#define NSAMPLE 32

// ---------------- scratch (no allocation allowed) ----------------
__device__ int   g_ball_idx[BATCH * NPOINT * NSAMPLE];
// k-major folded weights: g_wk[c][o]
__device__ float g_wk1[68 * 64];
__device__ float g_wk2[64 * 64];
__device__ float g_wk3[64 * 128];
__device__ float g_fb1[64];
__device__ float g_fb2[64];
__device__ float g_fb3[128];

// ---------------- packed f32x2 helpers (per-lane rn => bitwise == scalar) ---
__device__ __forceinline__ unsigned long long pk2(float lo, float hi) {
    unsigned long long r;
    asm("mov.b64 %0, {%1, %2};" : "=l"(r) : "f"(lo), "f"(hi));
    return r;
}
__device__ __forceinline__ void upk2(float& lo, float& hi, unsigned long long v) {
    asm("mov.b64 {%0, %1}, %2;" : "=f"(lo), "=f"(hi) : "l"(v));
}
__device__ __forceinline__ unsigned long long add2(unsigned long long a, unsigned long long b) {
    unsigned long long r;
    asm("add.rn.f32x2 %0, %1, %2;" : "=l"(r) : "l"(a), "l"(b));
    return r;
}
__device__ __forceinline__ unsigned long long mul2(unsigned long long a, unsigned long long b) {
    unsigned long long r;
    asm("mul.rn.f32x2 %0, %1, %2;" : "=l"(r) : "l"(a), "l"(b));
    return r;
}

// ---------------- fold BN-affine into weights (k-major output) -------------
__global__ void prep_kernel(const float* __restrict__ w1, const float* __restrict__ b1,
                            const float* __restrict__ g1, const float* __restrict__ bt1,
                            const float* __restrict__ w2, const float* __restrict__ b2,
                            const float* __restrict__ g2, const float* __restrict__ bt2,
                            const float* __restrict__ w3, const float* __restrict__ b3,
                            const float* __restrict__ g3, const float* __restrict__ bt3)
{
    int t = blockIdx.x * blockDim.x + threadIdx.x;
    int stride = gridDim.x * blockDim.x;
    const float inv = 1.0f / sqrtf(1.0f + 1e-5f);
    for (int i = t; i < 68 * 64; i += stride) {       // wk1[c][o], c=67 zero pad
        int c = i >> 6, o = i & 63;
        g_wk1[i] = (c < 67) ? (g1[o] * inv) * w1[o * 67 + c] : 0.0f;
    }
    for (int i = t; i < 64 * 64; i += stride) {       // wk2[c][o]
        int c = i >> 6, o = i & 63;
        g_wk2[i] = (g2[o] * inv) * w2[o * 64 + c];
    }
    for (int i = t; i < 64 * 128; i += stride) {      // wk3[c][o]
        int c = i >> 7, o = i & 127;
        g_wk3[i] = (g3[o] * inv) * w3[o * 64 + c];
    }
    for (int i = t; i < 64; i += stride) {
        g_fb1[i] = (g1[i] * inv) * b1[i] + bt1[i];
        g_fb2[i] = (g2[i] * inv) * b2[i] + bt2[i];
    }
    for (int i = t; i < 128; i += stride)
        g_fb3[i] = (g3[i] * inv) * b3[i] + bt3[i];
}

// ---------------- farthest point sampling ----------------
// One 512-thread block per batch, 16 pts/thread, blocked assignment (lane
// order == index order == warp order -> jnp.argmax first-max tie-break).
// ONE __syncthreads per iteration: warp leaders write to parity-double-
// buffered red[2][16]; every warp then redundantly reduces the 16 entries
// (REDUX + ballot + shfl) so no second barrier / broadcast word is needed.
// Distance math: packed f32x2 (per-lane rn) == bitwise the XLA scalar
// sequence dx*dx; +dy*dy; +dz*dz with p + (-c) == p - c exactly.
// dists >= +0 so float order == u32 bit order (argmax on bits).
__global__ void __launch_bounds__(512, 1)
fps_kernel(const float* __restrict__ xyz, float* __restrict__ out_xyz)
{
    extern __shared__ float sm[];
    float* sx = sm;
    float* sy = sm + NPTS;
    float* sz = sm + 2 * NPTS;
    __shared__ unsigned red_v[2][16];
    __shared__ int      red_i[2][16];

    int b = blockIdx.x, tid = threadIdx.x;
    const float* xb = xyz + (size_t)b * NPTS * 3;

    for (int p = tid; p < NPTS; p += 512) {
        sx[p] = xb[3 * p];
        sy[p] = xb[3 * p + 1];
        sz[p] = xb[3 * p + 2];
    }
    __syncthreads();

    int base = tid * 16;
    unsigned long long pxp[8], pyp[8], pzp[8];
    float dist[16];
#pragma unroll
    for (int k = 0; k < 8; k++) {
        pxp[k] = pk2(sx[base + 2 * k], sx[base + 2 * k + 1]);
        pyp[k] = pk2(sy[base + 2 * k], sy[base + 2 * k + 1]);
        pzp[k] = pk2(sz[base + 2 * k], sz[base + 2 * k + 1]);
    }
#pragma unroll
    for (int j = 0; j < 16; j++) dist[j] = 1e10f;

    int lane = tid & 31, w = tid >> 5;
    int far = 0;
    float* ob = out_xyz + (size_t)b * NPOINT * 3;

    for (int it = 0; it < NPOINT; it++) {
        float cx = sx[far], cy = sy[far], cz = sz[far];
        if (tid == 0) { ob[3 * it] = cx; ob[3 * it + 1] = cy; ob[3 * it + 2] = cz; }

        unsigned long long ncx = pk2(-cx, -cx);
        unsigned long long ncy = pk2(-cy, -cy);
        unsigned long long ncz = pk2(-cz, -cz);

        unsigned umax = 0u;
#pragma unroll
        for (int k = 0; k < 8; k++) {
            unsigned long long dx = add2(pxp[k], ncx);   // == px - cx (exact)
            unsigned long long dy = add2(pyp[k], ncy);
            unsigned long long dz = add2(pzp[k], ncz);
            unsigned long long s  = mul2(dx, dx);
            s = add2(s, mul2(dy, dy));
            s = add2(s, mul2(dz, dz));
            float d0, d1;
            upk2(d0, d1, s);
            float n0 = fminf(dist[2 * k],     d0);
            float n1 = fminf(dist[2 * k + 1], d1);
            dist[2 * k]     = n0;
            dist[2 * k + 1] = n1;
            unsigned u0 = __float_as_uint(n0), u1 = __float_as_uint(n1);
            umax = umax > u0 ? umax : u0;
            umax = umax > u1 ? umax : u1;
        }

        unsigned wmax = __reduce_max_sync(0xffffffffu, umax);
        unsigned ball = __ballot_sync(0xffffffffu, umax == wmax);
        int bank = it & 1;
        if (lane == (__ffs(ball) - 1)) {     // lowest lane = lowest index
            int bj = 0;
#pragma unroll
            for (int j = 15; j >= 0; j--)
                if (__float_as_uint(dist[j]) == wmax) bj = j;   // lowest j wins
            red_v[bank][w] = wmax;
            red_i[bank][w] = base + bj;
        }
        __syncthreads();
        // every warp reduces the 16 entries redundantly (lanes 16-31 mirror)
        unsigned v  = red_v[bank][lane & 15];
        int      vi = red_i[bank][lane & 15];
        unsigned m   = __reduce_max_sync(0xffffffffu, v);
        unsigned bal = __ballot_sync(0xffffffffu, v == m);
        far = __shfl_sync(0xffffffffu, vi, __ffs(bal) - 1);  // lowest warp = lowest idx
        // bank reused at it+2, after the it+1 barrier -> race-free
    }
}

// ---------------- ball query ----------------
__global__ void __launch_bounds__(256)
ballq_kernel(const float* __restrict__ xyz, const float* __restrict__ cxyz)
{
    __shared__ int sidx[8][NSAMPLE];
    int warp = threadIdx.x >> 5, lane = threadIdx.x & 31;
    int g = blockIdx.x * 8 + warp;          // 0 .. BATCH*NPOINT-1
    int b = g >> 11;

    const float* cp = cxyz + (size_t)g * 3;
    float cx = cp[0], cy = cp[1], cz = cp[2];
    const float* xb = xyz + (size_t)b * NPTS * 3;
    const float r2 = (float)(0.2 * 0.2);
    unsigned ltmask = (1u << lane) - 1u;

    int count = 0;
    for (int base = 0; base < NPTS; base += 32) {
        int p = base + lane;
        float xv = xb[3 * p], yv = xb[3 * p + 1], zv = xb[3 * p + 2];
        float dx = __fsub_rn(cx, xv);
        float dy = __fsub_rn(cy, yv);
        float dz = __fsub_rn(cz, zv);
        float d  = __fmul_rn(dx, dx);
        d = __fadd_rn(d, __fmul_rn(dy, dy));
        d = __fadd_rn(d, __fmul_rn(dz, dz));
        int in = (d <= r2) ? 1 : 0;
        unsigned m = __ballot_sync(0xffffffffu, in);
        if (in) {
            int pos = count + __popc(m & ltmask);
            if (pos < NSAMPLE) sidx[warp][pos] = p;
        }
        count += __popc(m);
        if (count >= NSAMPLE) break;        // warp-uniform
    }
    __syncwarp();
    int v = (lane < count) ? sidx[warp][lane] : sidx[warp][0];
    g_ball_idx[(size_t)g * NSAMPLE + lane] = v;
}

// ---------------- MLP as register-blocked GEMM ----------------
// Block: 256 threads, 8 centroids = 256 rows (samples). Activations live
// TRANSPOSED in smem (actT[k][row], row contiguous) so A-frags are 2 LDS.128
// of 8 consecutive rows; weights k-major (wk[k][o]) so B-frags are 2 LDS.128
// of 8 consecutive channels. Thread tile 8x8 -> 4 LDS.128 per 64 FMA:
// smem traffic 64B/cyc at full FMA issue (half of the 128B/cyc crossbar),
// vs 256B/cyc for the old broadcast scheme. Outputs stored transposed
// (relu'd) for the next layer. Layer3 fuses relu+max-pool via smem atomicMax
// on nonneg float bits.
#define CPB   8            // centroids per block
#define MROWS 256          // CPB * NSAMPLE

template<int CI, int CO>
__device__ __forceinline__ void gemm_layer(const float* __restrict__ in,
                                           const float* __restrict__ w,
                                           const float* __restrict__ bias,
                                           float* __restrict__ out,
                                           int rg, int cg)
{
    int cb = 8 * cg;
    float bb[8];
#pragma unroll
    for (int j = 0; j < 8; j++) bb[j] = bias[cb + j];
    float acc[8][8];
#pragma unroll
    for (int i = 0; i < 8; i++)
#pragma unroll
        for (int j = 0; j < 8; j++) acc[i][j] = bb[j];

    const float* ap = in + 8 * rg;
    const float* wp = w + cb;
#pragma unroll 2
    for (int k = 0; k < CI; k++) {
        float4 a0 = *(const float4*)(ap + k * MROWS);
        float4 a1 = *(const float4*)(ap + k * MROWS + 4);
        float4 b0 = *(const float4*)(wp + k * CO);
        float4 b1 = *(const float4*)(wp + k * CO + 4);
        float av[8] = {a0.x, a0.y, a0.z, a0.w, a1.x, a1.y, a1.z, a1.w};
        float bv[8] = {b0.x, b0.y, b0.z, b0.w, b1.x, b1.y, b1.z, b1.w};
#pragma unroll
        for (int i = 0; i < 8; i++)
#pragma unroll
            for (int j = 0; j < 8; j++)
                acc[i][j] = fmaf(av[i], bv[j], acc[i][j]);
    }
    // relu + transposed store: out[(cb+j)][8rg + i]
#pragma unroll
    for (int j = 0; j < 8; j++) {
        float4 v0, v1;
        v0.x = fmaxf(acc[0][j], 0.0f); v0.y = fmaxf(acc[1][j], 0.0f);
        v0.z = fmaxf(acc[2][j], 0.0f); v0.w = fmaxf(acc[3][j], 0.0f);
        v1.x = fmaxf(acc[4][j], 0.0f); v1.y = fmaxf(acc[5][j], 0.0f);
        v1.z = fmaxf(acc[6][j], 0.0f); v1.w = fmaxf(acc[7][j], 0.0f);
        *(float4*)(out + (cb + j) * MROWS + 8 * rg)     = v0;
        *(float4*)(out + (cb + j) * MROWS + 8 * rg + 4) = v1;
    }
}

__global__ void __launch_bounds__(256, 1)
mlp_kernel(const float* __restrict__ xyz, const float* __restrict__ feats,
           const float* __restrict__ cxyz, float* __restrict__ out_feats)
{
    extern __shared__ float s[];
    float* xT  = s;                    // [68][256], reused as y2T[64][256]
    float* y1T = xT + 68 * MROWS;      // [64][256]
    float* w1  = y1T + 64 * MROWS;     // [68][64]
    float* w2  = w1 + 68 * 64;         // [64][64]
    float* w3  = w2 + 64 * 64;         // [64][128]
    float* sb1 = w3 + 64 * 128;        // 64
    float* sb2 = sb1 + 64;             // 64
    float* sb3 = sb2 + 64;             // 128
    int*   pb  = (int*)(sb3 + 128);    // [8][128] pooled bits

    int tid = threadIdx.x;
    for (int i = tid; i < 68 * 64;  i += 256) w1[i] = g_wk1[i];
    for (int i = tid; i < 64 * 64;  i += 256) w2[i] = g_wk2[i];
    for (int i = tid; i < 64 * 128; i += 256) w3[i] = g_wk3[i];
    if (tid < 64)  { sb1[tid] = g_fb1[tid]; sb2[tid] = g_fb2[tid]; }
    if (tid < 128)   sb3[tid] = g_fb3[tid];
    for (int i = tid; i < CPB * 128; i += 256) pb[i] = 0;

    // gather: thread = row (one sample of one centroid)
    {
        int r   = tid;
        int ci  = r >> 5, smp = r & 31;
        int g   = blockIdx.x * CPB + ci;
        int b   = g >> 11;
        const float* cp = cxyz + (size_t)g * 3;
        float cx = cp[0], cy = cp[1], cz = cp[2];
        int idx = g_ball_idx[(size_t)g * NSAMPLE + smp];
        const float* pp = xyz + (size_t)(b * NPTS + idx) * 3;
        xT[0 * MROWS + r] = (pp[0] - cx) / 0.2f;
        xT[1 * MROWS + r] = (pp[1] - cy) / 0.2f;
        xT[2 * MROWS + r] = (pp[2] - cz) / 0.2f;
        const float4* pf = (const float4*)(feats + (size_t)(b * NPTS + idx) * 64);
#pragma unroll
        for (int q = 0; q < 16; q++) {
            float4 f = pf[q];
            xT[(3 + 4 * q) * MROWS + r] = f.x;
            xT[(4 + 4 * q) * MROWS + r] = f.y;
            xT[(5 + 4 * q) * MROWS + r] = f.z;
            xT[(6 + 4 * q) * MROWS + r] = f.w;
        }
        xT[67 * MROWS + r] = 0.0f;
    }
    __syncthreads();

    int rg = tid >> 3, cg = tid & 7;   // 32 row-groups x 8 col-groups

    gemm_layer<68, 64>(xT, w1, sb1, y1T, rg, cg);
    __syncthreads();
    gemm_layer<64, 64>(y1T, w2, sb2, xT, rg, cg);   // y2T aliases xT
    __syncthreads();

    // layer3 (+relu+max-pool fused), two 64-col halves
#pragma unroll
    for (int h = 0; h < 2; h++) {
        int cb = 64 * h + 8 * cg;
        float acc[8][8];
#pragma unroll
        for (int j = 0; j < 8; j++) {
            float bj = sb3[cb + j];
#pragma unroll
            for (int i = 0; i < 8; i++) acc[i][j] = bj;
        }
        const float* ap = xT + 8 * rg;
        const float* wp = w3 + cb;
#pragma unroll 2
        for (int k = 0; k < 64; k++) {
            float4 a0 = *(const float4*)(ap + k * MROWS);
            float4 a1 = *(const float4*)(ap + k * MROWS + 4);
            float4 b0 = *(const float4*)(wp + k * 128);
            float4 b1 = *(const float4*)(wp + k * 128 + 4);
            float av[8] = {a0.x, a0.y, a0.z, a0.w, a1.x, a1.y, a1.z, a1.w};
            float bv[8] = {b0.x, b0.y, b0.z, b0.w, b1.x, b1.y, b1.z, b1.w};
#pragma unroll
            for (int i = 0; i < 8; i++)
#pragma unroll
                for (int j = 0; j < 8; j++)
                    acc[i][j] = fmaf(av[i], bv[j], acc[i][j]);
        }
        int cent = rg >> 2;            // 4 row-groups per centroid
#pragma unroll
        for (int j = 0; j < 8; j++) {
            float m = acc[0][j];
#pragma unroll
            for (int i = 1; i < 8; i++) m = fmaxf(m, acc[i][j]);
            m = fmaxf(m, 0.0f);        // relu-then-max == max-then-relu
            atomicMax(&pb[cent * 128 + cb + j], __float_as_int(m));  // nonneg bits
        }
    }
    __syncthreads();

    for (int i = tid; i < CPB * 128; i += 256) {
        int ci = i >> 7, col = i & 127;
        int g = blockIdx.x * CPB + ci;
        out_feats[(size_t)g * 128 + col] = __int_as_float(pb[i]);
    }
}

// ---------------- launch ----------------
extern "C" void kernel_launch(void* const* d_in, const int* in_sizes, int n_in,
                              void* d_out, int out_size)
{
    const float* xyz   = (const float*)d_in[0];
    const float* feats = (const float*)d_in[1];

    float* out       = (float*)d_out;
    float* out_xyz   = out;                          // [B, NPOINT, 3]
    float* out_feats = out + BATCH * NPOINT * 3;     // [B, NPOINT, 128]

    const int MLP_SMEM = (68 * 256 + 64 * 256 + 68 * 64 + 64 * 64 + 64 * 128
                          + 64 + 64 + 128) * 4 + CPB * 128 * 4;   // 206848B

    cudaFuncSetAttribute(fps_kernel, cudaFuncAttributeMaxDynamicSharedMemorySize, 3 * NPTS * 4);
    cudaFuncSetAttribute(mlp_kernel, cudaFuncAttributeMaxDynamicSharedMemorySize, MLP_SMEM);

    prep_kernel<<<32, 256>>>((const float*)d_in[2],  (const float*)d_in[3],
                             (const float*)d_in[4],  (const float*)d_in[5],
                             (const float*)d_in[6],  (const float*)d_in[7],
                             (const float*)d_in[8],  (const float*)d_in[9],
                             (const float*)d_in[10], (const float*)d_in[11],
                             (const float*)d_in[12], (const float*)d_in[13]);

    fps_kernel<<<BATCH, 512, 3 * NPTS * 4>>>(xyz, out_xyz);

    ballq_kernel<<<(BATCH * NPOINT) / 8, 256>>>(xyz, out_xyz);

    mlp_kernel<<<(BATCH * NPOINT) / CPB, 256, MLP_SMEM>>>(xyz, feats, out_xyz, out_feats);
}